// round 14
// baseline (speedup 1.0000x reference)
#include <cuda_runtime.h>
#include <cuda_fp16.h>
#include <math.h>
#include <stdint.h>

#define BATCH  2
#define SEQ    2048
#define DMODEL 2048
#define NH     16
#define NKV    4
#define HD     128
#define EQKV   3072
#define TOK    (BATCH*SEQ)

// Scratch (device globals; no allocation allowed) — fp16
__device__ __half g_qh   [(size_t)TOK * NH  * HD];   // normed, roped, scaled
__device__ __half g_kh   [(size_t)TOK * NKV * HD];   // normed, roped
__device__ __half g_vh   [(size_t)TOK * NKV * HD];
__device__ __half g_yh   [(size_t)TOK * NH  * HD];
__device__ __half g_xh   [(size_t)TOK * DMODEL];
__device__ __half g_wqkvh[(size_t)EQKV * DMODEL];
__device__ __half g_woh  [(size_t)DMODEL * NH * HD];

__device__ __forceinline__ uint32_t s2u(const void* p) {
    uint32_t a;
    asm("{ .reg .u64 t; cvta.to.shared.u64 t, %1; cvt.u32.u64 %0, t; }"
        : "=r"(a) : "l"(p));
    return a;
}
__device__ __forceinline__ void mma_f16(float* c, const uint32_t* a, const uint32_t* b) {
    asm volatile(
        "mma.sync.aligned.m16n8k16.row.col.f32.f16.f16.f32 "
        "{%0,%1,%2,%3}, {%4,%5,%6,%7}, {%8,%9}, {%0,%1,%2,%3};"
        : "+f"(c[0]), "+f"(c[1]), "+f"(c[2]), "+f"(c[3])
        : "r"(a[0]), "r"(a[1]), "r"(a[2]), "r"(a[3]),
          "r"(b[0]), "r"(b[1]));
}
__device__ __forceinline__ void ldsm4(uint32_t* r, uint32_t a) {
    asm volatile("ldmatrix.sync.aligned.m8n8.x4.shared.b16 {%0,%1,%2,%3}, [%4];"
        : "=r"(r[0]), "=r"(r[1]), "=r"(r[2]), "=r"(r[3]) : "r"(a));
}
__device__ __forceinline__ void ldsm4t(uint32_t* r, uint32_t a) {
    asm volatile("ldmatrix.sync.aligned.m8n8.x4.trans.shared.b16 {%0,%1,%2,%3}, [%4];"
        : "=r"(r[0]), "=r"(r[1]), "=r"(r[2]), "=r"(r[3]) : "r"(a));
}
__device__ __forceinline__ void cp16(uint32_t smem_dst, const void* gptr) {
    asm volatile("cp.async.cg.shared.global [%0], [%1], 16;"
                 :: "r"(smem_dst), "l"(gptr) : "memory");
}
#define CP_COMMIT() asm volatile("cp.async.commit_group;" ::: "memory")
#define CP_WAIT0()  asm volatile("cp.async.wait_group 0;" ::: "memory")
#define CP_WAIT1()  asm volatile("cp.async.wait_group 1;" ::: "memory")
__device__ __forceinline__ uint32_t h2u(__half2 h) {
    return *reinterpret_cast<uint32_t*>(&h);
}
__device__ __forceinline__ uint32_t ex2_h2(__half2 s) {
    uint32_t r;
    asm("ex2.approx.f16x2 %0, %1;" : "=r"(r) : "r"(h2u(s)));
    return r;
}

// ---------------------------------------------------------------------------
// Merged fp32 -> fp16 conversion of x, wqkv, wo in one launch.
// ---------------------------------------------------------------------------
#define N_X  ((size_t)TOK * DMODEL)
#define N_W1 ((size_t)EQKV * DMODEL)
#define N_W2 ((size_t)DMODEL * NH * HD)

__global__ __launch_bounds__(256)
void to_half_all(const float* __restrict__ x, const float* __restrict__ wqkv,
                 const float* __restrict__ wo)
{
    size_t i = ((size_t)blockIdx.x * 256 + threadIdx.x) * 4;
    const float* s; __half* d; size_t off;
    if (i < N_X)            { s = x;    d = g_xh;    off = i; }
    else if (i < N_X + N_W1){ s = wqkv; d = g_wqkvh; off = i - N_X; }
    else                    { s = wo;   d = g_woh;   off = i - N_X - N_W1; }
    float4 v = *(const float4*)(s + off);
    __half2* dp = (__half2*)(d + off);
    dp[0] = __floats2half2_rn(v.x, v.y);
    dp[1] = __floats2half2_rn(v.z, v.w);
}

// ---------------------------------------------------------------------------
// fp16 mma.sync GEMM (NT): BK=32, 4-stage cp.async, XOR-swizzled smem.
// mode 1: fused qkv epilogue (RMSNorm + RoPE + scale per head-tile).
// (unchanged from R13)
// ---------------------------------------------------------------------------
#define GTILEH (128 * 32)
#define NST 4
#define GSMEM (NST * 2 * GTILEH * 2)      // 65536 B

__global__ __launch_bounds__(128)
void gemm_hp(const __half* __restrict__ A, const __half* __restrict__ Bm,
             float* __restrict__ Cf, int M, int N, int K, int mode,
             const float* __restrict__ freqs,
             const float* __restrict__ qw, const float* __restrict__ kw)
{
    extern __shared__ __half smh[];
    __half* As = smh;
    __half* Bs = smh + NST * GTILEH;

    const int tid  = threadIdx.x;
    const int lane = tid & 31;
    const int wid  = tid >> 5;
    const int wm   = wid & 1;
    const int wn   = wid >> 1;
    const int gr   = lane >> 2;
    const int qq   = lane & 3;
    const int row0 = blockIdx.y * 128;
    const int col0 = blockIdx.x * 128;

    const int kq = tid & 3, rb = tid >> 2;
    const __half* Ag = A  + (size_t)(row0 + rb) * K + kq * 8;
    const __half* Bg = Bm + (size_t)(col0 + rb) * K + kq * 8;
    const uint32_t sA = s2u(As), sB = s2u(Bs);
    const uint32_t d0 = (uint32_t)(rb * 32 + ((kq ^ ((rb >> 1) & 3)) << 3)) * 2;

    const int rowA = lane & 15, hiA = lane >> 4;
    const int rowB = (lane & 7) + 8 * (lane >> 4), hiB = (lane >> 3) & 1;
    uint32_t aOff[4], bOff[4];
    int aSw[4], bSw[4];
#pragma unroll
    for (int i = 0; i < 4; ++i) {
        int r = wm * 64 + i * 16 + rowA;
        aOff[i] = (uint32_t)r * 64; aSw[i] = (r >> 1) & 3;
    }
#pragma unroll
    for (int p = 0; p < 4; ++p) {
        int r = wn * 64 + p * 16 + rowB;
        bOff[p] = (uint32_t)r * 64; bSw[p] = (r >> 1) & 3;
    }

    float acc[4][8][4];
#pragma unroll
    for (int i = 0; i < 4; ++i)
#pragma unroll
        for (int j = 0; j < 8; ++j)
#pragma unroll
            for (int v = 0; v < 4; ++v) acc[i][j][v] = 0.f;

    const int nk = K >> 5;

    auto issue = [&](int st) {
        const uint32_t ab = sA + (uint32_t)((st % NST) * GTILEH) * 2 + d0;
        const uint32_t bb = sB + (uint32_t)((st % NST) * GTILEH) * 2 + d0;
        const int kc = st << 5;
#pragma unroll
        for (int j = 0; j < 4; ++j) {
            cp16(ab + j * 2048, Ag + (size_t)(32 * j) * K + kc);
            cp16(bb + j * 2048, Bg + (size_t)(32 * j) * K + kc);
        }
    };

    issue(0); CP_COMMIT();
    issue(1); CP_COMMIT();
    issue(2); CP_COMMIT();

    for (int it = 0; it < nk; ++it) {
        CP_WAIT1();
        __syncthreads();
        if (it + 3 < nk) issue(it + 3);
        CP_COMMIT();

        const uint32_t aS = sA + (uint32_t)((it % NST) * GTILEH) * 2;
        const uint32_t bS = sB + (uint32_t)((it % NST) * GTILEH) * 2;
#pragma unroll
        for (int kk = 0; kk < 2; ++kk) {
            uint32_t af[4][4], bf[4][4];
#pragma unroll
            for (int i = 0; i < 4; ++i)
                ldsm4(af[i], aS + aOff[i] + (uint32_t)(((kk * 2 + hiA) ^ aSw[i]) << 4));
#pragma unroll
            for (int p = 0; p < 4; ++p)
                ldsm4(bf[p], bS + bOff[p] + (uint32_t)(((kk * 2 + hiB) ^ bSw[p]) << 4));
#pragma unroll
            for (int i = 0; i < 4; ++i)
#pragma unroll
                for (int j = 0; j < 8; ++j)
                    mma_f16(acc[i][j], af[i], &bf[j >> 1][(j & 1) * 2]);
        }
    }

    if (mode == 0) {
        const int egc = qq * 2;
#pragma unroll
        for (int i = 0; i < 4; ++i) {
#pragma unroll
            for (int j = 0; j < 8; ++j) {
                const size_t base = (size_t)(row0 + wm * 64 + i * 16 + gr) * N +
                                    col0 + wn * 64 + j * 8 + egc;
                *(float2*)(Cf + base) = make_float2(acc[i][j][0], acc[i][j][1]);
                *(float2*)(Cf + base + 8 * (size_t)N) = make_float2(acc[i][j][2], acc[i][j][3]);
            }
        }
        return;
    }

    // ---- fused qkv epilogue ----
    CP_WAIT0();
    __syncthreads();
    float* red = (float*)smh;
    const bool isV = (col0 >= DMODEL + NKV * HD);
    const bool isQ = (col0 < DMODEL);

    if (!isV) {
#pragma unroll
        for (int i = 0; i < 4; ++i) {
            float p0 = 0.f, p1 = 0.f;
#pragma unroll
            for (int j = 0; j < 8; ++j) {
                p0 += acc[i][j][0] * acc[i][j][0] + acc[i][j][1] * acc[i][j][1];
                p1 += acc[i][j][2] * acc[i][j][2] + acc[i][j][3] * acc[i][j][3];
            }
            p0 += __shfl_xor_sync(0xffffffffu, p0, 1);
            p0 += __shfl_xor_sync(0xffffffffu, p0, 2);
            p1 += __shfl_xor_sync(0xffffffffu, p1, 1);
            p1 += __shfl_xor_sync(0xffffffffu, p1, 2);
            if (qq == 0) {
                red[(wm * 64 + i * 16 + gr) * 2 + wn]     = p0;
                red[(wm * 64 + i * 16 + gr + 8) * 2 + wn] = p1;
            }
        }
        __syncthreads();
    }

    const float* nw = isQ ? qw : kw;
    const float qs = isQ ? (0.08838834764831845f * 1.44269504088896341f) : 1.0f;

#pragma unroll
    for (int i = 0; i < 4; ++i) {
        const int lra = wm * 64 + i * 16 + gr;
        const int lrb = lra + 8;
        const int ra = row0 + lra, rbg = row0 + lrb;
        float rsA = 1.f, rsB = 1.f;
        if (!isV) {
            rsA = rsqrtf((red[lra * 2] + red[lra * 2 + 1]) * (1.f / HD) + 1e-5f);
            rsB = rsqrtf((red[lrb * 2] + red[lrb * 2 + 1]) * (1.f / HD) + 1e-5f);
        }
        const int sa = ra & (SEQ - 1), sb = rbg & (SEQ - 1);
#pragma unroll
        for (int j = 0; j < 8; ++j) {
            const int cb = wn * 64 + j * 8 + 2 * qq;
            if (isV) {
                const int vc = (col0 - DMODEL - NKV * HD) + cb;
                *(__half2*)(g_vh + (size_t)ra  * (NKV * HD) + vc) =
                    __floats2half2_rn(acc[i][j][0], acc[i][j][1]);
                *(__half2*)(g_vh + (size_t)rbg * (NKV * HD) + vc) =
                    __floats2half2_rn(acc[i][j][2], acc[i][j][3]);
            } else {
                const float we = nw[cb], wo_ = nw[cb + 1];
                float2 fa = *(const float2*)(freqs + (size_t)sa * HD + cb);
                float xe = acc[i][j][0] * rsA * we;
                float xo = acc[i][j][1] * rsA * wo_;
                float oe = xe * fa.x - xo * fa.y;
                float oo = xo * fa.x + xe * fa.y;
                __half2 ha = __floats2half2_rn(oe * qs, oo * qs);
                float2 fb = *(const float2*)(freqs + (size_t)sb * HD + cb);
                xe = acc[i][j][2] * rsB * we;
                xo = acc[i][j][3] * rsB * wo_;
                oe = xe * fb.x - xo * fb.y;
                oo = xo * fb.x + xe * fb.y;
                __half2 hb = __floats2half2_rn(oe * qs, oo * qs);
                if (isQ) {
                    *(__half2*)(g_qh + (size_t)ra  * (NH * HD) + col0 + cb) = ha;
                    *(__half2*)(g_qh + (size_t)rbg * (NH * HD) + col0 + cb) = hb;
                } else {
                    const int kc = (col0 - DMODEL) + cb;
                    *(__half2*)(g_kh + (size_t)ra  * (NKV * HD) + kc) = ha;
                    *(__half2*)(g_kh + (size_t)rbg * (NKV * HD) + kc) = hb;
                }
            }
        }
    }
}

// ---------------------------------------------------------------------------
// Flash attention: 128-row Q tile, 256 threads (8 warps), fp16 mma + ldmatrix.
// Fixed-base softmax folded into accumulator init (-6); ex2.approx.f16x2;
// register-resident P; hoisted Q fragments; l via ones-column MMA.
// ---------------------------------------------------------------------------
#define SM_BIAS 6.0f
#define QS 136
#define KS 136
#define VS 152
#define KT (64 * KS)
#define VT (64 * VS)
#define ASMEM ((128 * QS + 2 * KT + 2 * VT) * 2)   // 108544 B

__global__ __launch_bounds__(256, 1)
void attn_hp()
{
    extern __shared__ __half smh[];
    __half* Qsm = smh;
    __half* Ksm = Qsm + 128 * QS;
    __half* Vsm = Ksm + 2 * KT;
    const uint32_t qB = s2u(Qsm), kB0 = s2u(Ksm), vB0 = s2u(Vsm);

    const int qt  = (int)gridDim.x - 1 - (int)blockIdx.x;   // big tiles first
    const int h   = blockIdx.y;
    const int b   = blockIdx.z;
    const int kvh = h >> 2;
    const int q0  = qt * 128;
    const int tid = threadIdx.x;
    const int w   = tid >> 5;       // 0..7
    const int lane = tid & 31;
    const int gr  = lane >> 2;
    const int qq  = lane & 3;
    const int r0l = w * 16 + gr;    // local q row (0..127)
    const int r1l = r0l + 8;

    const int rowA = lane & 15;
    const int rowB = (lane & 7) + 8 * (lane >> 4);
    const int colA = 8 * (lane >> 4), colB = 8 * ((lane >> 3) & 1);
    const uint32_t qAddr = qB + (uint32_t)((w * 16 + rowA) * QS + colA) * 2;
    const uint32_t kOff  = (uint32_t)(rowB * KS + colB) * 2;
    const uint32_t vOff  = (uint32_t)((lane & 15) * VS + 8 * (lane >> 4)) * 2;

    // staging (256 threads): K/V tile 64x128 -> 4 cp16/thread; Q 128x128 -> 8
    const int sr = tid >> 4, sc = (tid & 15) * 8;
    auto stageK = [&](int kt, int buf) {
        const __half* src = g_kh + (size_t)(b * SEQ + kt * 64 + sr) * (NKV * HD) + kvh * HD + sc;
        uint32_t dst = kB0 + (uint32_t)(buf * KT) * 2 + (uint32_t)(sr * KS + sc) * 2;
#pragma unroll
        for (int it = 0; it < 4; ++it)
            cp16(dst + (uint32_t)(16 * it * KS) * 2, src + (size_t)(16 * it) * (NKV * HD));
    };
    auto stageV = [&](int kt, int buf) {
        const __half* src = g_vh + (size_t)(b * SEQ + kt * 64 + sr) * (NKV * HD) + kvh * HD + sc;
        uint32_t dst = vB0 + (uint32_t)(buf * VT) * 2 + (uint32_t)(sr * VS + sc) * 2;
#pragma unroll
        for (int it = 0; it < 4; ++it)
            cp16(dst + (uint32_t)(16 * it * VS) * 2, src + (size_t)(16 * it) * (NKV * HD));
    };

    // prologue: Q + K0 + V0; ones-column init in both V buffers
    {
        const __half* src = g_qh + (size_t)(b * SEQ + q0 + sr) * (NH * HD) + h * HD + sc;
        uint32_t dst = qB + (uint32_t)(sr * QS + sc) * 2;
#pragma unroll
        for (int it = 0; it < 8; ++it)
            cp16(dst + (uint32_t)(16 * it * QS) * 2, src + (size_t)(16 * it) * (NH * HD));
        stageK(0, 0); stageV(0, 0);
        CP_COMMIT();
        for (int idx = tid; idx < 2 * 64 * 16; idx += 256) {
            int bu = idx >> 10, r = (idx >> 4) & 63, c = idx & 15;
            Vsm[bu * VT + r * VS + 128 + c] = (c == 0) ? __float2half(1.f) : __float2half(0.f);
        }
        CP_WAIT0();
        __syncthreads();
    }

    // hoist Q fragments
    uint32_t qf[8][4];
#pragma unroll
    for (int kk = 0; kk < 8; ++kk)
        ldsm4(qf[kk], qAddr + (uint32_t)(kk * 16) * 2);

    float O[17][4];
#pragma unroll
    for (int nt = 0; nt < 17; ++nt)
#pragma unroll
        for (int v = 0; v < 4; ++v) O[nt][v] = 0.f;

    const int kend = 2 * qt + 1;
    for (int kt = 0; kt <= kend; ++kt) {
        if (kt < kend) {
            stageK(kt + 1, (kt + 1) & 1);
            stageV(kt + 1, (kt + 1) & 1);
            CP_COMMIT();
        }
        const uint32_t kAddr = kB0 + (uint32_t)((kt & 1) * KT) * 2 + kOff;
        const uint32_t vAddr = vB0 + (uint32_t)((kt & 1) * VT) * 2 + vOff;

        // S = Q K^T  (accumulator pre-biased to -SM_BIAS)
        float s[8][4];
#pragma unroll
        for (int nt = 0; nt < 8; ++nt)
#pragma unroll
            for (int v = 0; v < 4; ++v) s[nt][v] = -SM_BIAS;
#pragma unroll
        for (int kk = 0; kk < 8; ++kk) {
            uint32_t bf[4][4];
#pragma unroll
            for (int p = 0; p < 4; ++p)
                ldsm4(bf[p], kAddr + (uint32_t)(p * 16 * KS + kk * 16) * 2);
#pragma unroll
            for (int nt = 0; nt < 8; ++nt)
                mma_f16(s[nt], qf[kk], &bf[nt >> 1][(nt & 1) * 2]);
        }

        // causal mask (last two kt tiles); koff = offset of this k tile vs q0
        if (kt >= kend - 1) {
            const int koff = (kt - 2 * qt) * 64;   // 0 or 64
#pragma unroll
            for (int nt = 0; nt < 8; ++nt) {
                int cb = koff + nt * 8 + 2 * qq;
                if (cb     > r0l) s[nt][0] = -1e30f;
                if (cb + 1 > r0l) s[nt][1] = -1e30f;
                if (cb     > r1l) s[nt][2] = -1e30f;
                if (cb + 1 > r1l) s[nt][3] = -1e30f;
            }
        }
        // p = 2^s via f16x2 MUFU (bias already in s)
        uint32_t pa[8], pb[8];
#pragma unroll
        for (int nt = 0; nt < 8; ++nt) {
            pa[nt] = ex2_h2(__floats2half2_rn(s[nt][0], s[nt][1]));
            pb[nt] = ex2_h2(__floats2half2_rn(s[nt][2], s[nt][3]));
        }

        // O += P V (+ l via ones column)
#pragma unroll
        for (int kk = 0; kk < 4; ++kk) {
            uint32_t af[4] = {pa[2 * kk], pb[2 * kk], pa[2 * kk + 1], pb[2 * kk + 1]};
            uint32_t bf[8][4], b8[4];
#pragma unroll
            for (int p = 0; p < 8; ++p)
                ldsm4t(bf[p], vAddr + (uint32_t)(kk * 16 * VS + p * 16) * 2);
            ldsm4t(b8, vAddr + (uint32_t)(kk * 16 * VS + 128) * 2);
#pragma unroll
            for (int nt = 0; nt < 16; ++nt)
                mma_f16(O[nt], af, &bf[nt >> 1][(nt & 1) * 2]);
            mma_f16(O[16], af, &b8[0]);
        }

        if (kt < kend) {
            CP_WAIT0();
            __syncthreads();
        }
    }

    float l0 = __shfl_sync(0xffffffffu, O[16][0], lane & ~3);
    float l1 = __shfl_sync(0xffffffffu, O[16][2], lane & ~3);
    float inv0 = 1.f / l0, inv1 = 1.f / l1;
    __half* y0 = g_yh + (size_t)(b * SEQ + q0 + r0l) * (NH * HD) + h * HD;
    __half* y1 = g_yh + (size_t)(b * SEQ + q0 + r1l) * (NH * HD) + h * HD;
#pragma unroll
    for (int nt = 0; nt < 16; ++nt) {
        *(__half2*)(y0 + nt * 8 + 2 * qq) = __floats2half2_rn(O[nt][0] * inv0, O[nt][1] * inv0);
        *(__half2*)(y1 + nt * 8 + 2 * qq) = __floats2half2_rn(O[nt][2] * inv1, O[nt][3] * inv1);
    }
}

// ---------------------------------------------------------------------------
extern "C" void kernel_launch(void* const* d_in, const int* in_sizes, int n_in,
                              void* d_out, int out_size)
{
    const float* x    = (const float*)d_in[0];
    const float* fr   = (const float*)d_in[1];
    const float* wqkv = (const float*)d_in[3];
    const float* wo   = (const float*)d_in[4];
    const float* qw   = (const float*)d_in[5];
    const float* kw   = (const float*)d_in[6];
    float* out = (float*)d_out;

    __half *yh_p, *xh_p, *wqkvh_p, *woh_p;
    cudaGetSymbolAddress((void**)&yh_p,    g_yh);
    cudaGetSymbolAddress((void**)&xh_p,    g_xh);
    cudaGetSymbolAddress((void**)&wqkvh_p, g_wqkvh);
    cudaGetSymbolAddress((void**)&woh_p,   g_woh);

    // 0) Convert inputs/weights to fp16 (single launch)
    const size_t ntot = N_X + N_W1 + N_W2;
    to_half_all<<<(unsigned)(ntot / 1024), 256>>>(x, wqkv, wo);

    cudaFuncSetAttribute(gemm_hp, cudaFuncAttributeMaxDynamicSharedMemorySize, GSMEM);
    cudaFuncSetAttribute(attn_hp, cudaFuncAttributeMaxDynamicSharedMemorySize, ASMEM);

    // 1) QKV projection + fused RMSNorm/RoPE/scale epilogue
    gemm_hp<<<dim3(EQKV / 128, TOK / 128), 128, GSMEM>>>(
        xh_p, wqkvh_p, nullptr, TOK, EQKV, DMODEL, 1, fr, qw, kw);

    // 2) Causal GQA flash attention (128-row q tiles)
    attn_hp<<<dim3(SEQ / 128, NH, BATCH), 256, ASMEM>>>();

    // 3) Output projection (fp32 out)
    gemm_hp<<<dim3(DMODEL / 128, TOK / 128), 128, GSMEM>>>(
        yh_p, woh_p, out, TOK, DMODEL, DMODEL, 0, nullptr, nullptr, nullptr);
}

// round 15
// speedup vs baseline: 1.0193x; 1.0193x over previous
#include <cuda_runtime.h>
#include <cuda_fp16.h>
#include <math.h>
#include <stdint.h>

#define BATCH  2
#define SEQ    2048
#define DMODEL 2048
#define NH     16
#define NKV    4
#define HD     128
#define EQKV   3072
#define TOK    (BATCH*SEQ)

// Scratch (device globals; no allocation allowed) — fp16
__device__ __half g_qh   [(size_t)TOK * NH  * HD];   // normed, roped, scaled
__device__ __half g_kh   [(size_t)TOK * NKV * HD];   // normed, roped
__device__ __half g_vh   [(size_t)TOK * NKV * HD];
__device__ __half g_yh   [(size_t)TOK * NH  * HD];
__device__ __half g_xh   [(size_t)TOK * DMODEL];
__device__ __half g_wqkvh[(size_t)EQKV * DMODEL];
__device__ __half g_woh  [(size_t)DMODEL * NH * HD];

__device__ __forceinline__ uint32_t s2u(const void* p) {
    uint32_t a;
    asm("{ .reg .u64 t; cvta.to.shared.u64 t, %1; cvt.u32.u64 %0, t; }"
        : "=r"(a) : "l"(p));
    return a;
}
__device__ __forceinline__ void mma_f16(float* c, const uint32_t* a, const uint32_t* b) {
    asm volatile(
        "mma.sync.aligned.m16n8k16.row.col.f32.f16.f16.f32 "
        "{%0,%1,%2,%3}, {%4,%5,%6,%7}, {%8,%9}, {%0,%1,%2,%3};"
        : "+f"(c[0]), "+f"(c[1]), "+f"(c[2]), "+f"(c[3])
        : "r"(a[0]), "r"(a[1]), "r"(a[2]), "r"(a[3]),
          "r"(b[0]), "r"(b[1]));
}
__device__ __forceinline__ void ldsm4(uint32_t* r, uint32_t a) {
    asm volatile("ldmatrix.sync.aligned.m8n8.x4.shared.b16 {%0,%1,%2,%3}, [%4];"
        : "=r"(r[0]), "=r"(r[1]), "=r"(r[2]), "=r"(r[3]) : "r"(a));
}
__device__ __forceinline__ void ldsm4t(uint32_t* r, uint32_t a) {
    asm volatile("ldmatrix.sync.aligned.m8n8.x4.trans.shared.b16 {%0,%1,%2,%3}, [%4];"
        : "=r"(r[0]), "=r"(r[1]), "=r"(r[2]), "=r"(r[3]) : "r"(a));
}
__device__ __forceinline__ void cp16(uint32_t smem_dst, const void* gptr) {
    asm volatile("cp.async.cg.shared.global [%0], [%1], 16;"
                 :: "r"(smem_dst), "l"(gptr) : "memory");
}
#define CP_COMMIT() asm volatile("cp.async.commit_group;" ::: "memory")
#define CP_WAIT0()  asm volatile("cp.async.wait_group 0;" ::: "memory")
#define CP_WAIT1()  asm volatile("cp.async.wait_group 1;" ::: "memory")
__device__ __forceinline__ uint32_t h2u(__half2 h) {
    return *reinterpret_cast<uint32_t*>(&h);
}
__device__ __forceinline__ float ex2f(float x) {
    float r;
    asm("ex2.approx.f32 %0, %1;" : "=f"(r) : "f"(x));
    return r;
}

// ---------------------------------------------------------------------------
// Merged fp32 -> fp16 conversion of x, wqkv, wo in one launch.
// ---------------------------------------------------------------------------
#define N_X  ((size_t)TOK * DMODEL)
#define N_W1 ((size_t)EQKV * DMODEL)
#define N_W2 ((size_t)DMODEL * NH * HD)

__global__ __launch_bounds__(256)
void to_half_all(const float* __restrict__ x, const float* __restrict__ wqkv,
                 const float* __restrict__ wo)
{
    size_t i = ((size_t)blockIdx.x * 256 + threadIdx.x) * 4;
    const float* s; __half* d; size_t off;
    if (i < N_X)            { s = x;    d = g_xh;    off = i; }
    else if (i < N_X + N_W1){ s = wqkv; d = g_wqkvh; off = i - N_X; }
    else                    { s = wo;   d = g_woh;   off = i - N_X - N_W1; }
    float4 v = *(const float4*)(s + off);
    __half2* dp = (__half2*)(d + off);
    dp[0] = __floats2half2_rn(v.x, v.y);
    dp[1] = __floats2half2_rn(v.z, v.w);
}

// ---------------------------------------------------------------------------
// fp16 mma.sync GEMM (NT): BK=32, 4-stage cp.async, XOR-swizzled smem.
// mode 1: fused qkv epilogue (RMSNorm + RoPE + scale per head-tile).
// ---------------------------------------------------------------------------
#define GTILEH (128 * 32)
#define NST 4
#define GSMEM (NST * 2 * GTILEH * 2)      // 65536 B

__global__ __launch_bounds__(128)
void gemm_hp(const __half* __restrict__ A, const __half* __restrict__ Bm,
             float* __restrict__ Cf, int M, int N, int K, int mode,
             const float* __restrict__ freqs,
             const float* __restrict__ qw, const float* __restrict__ kw)
{
    extern __shared__ __half smh[];
    __half* As = smh;
    __half* Bs = smh + NST * GTILEH;

    const int tid  = threadIdx.x;
    const int lane = tid & 31;
    const int wid  = tid >> 5;
    const int wm   = wid & 1;
    const int wn   = wid >> 1;
    const int gr   = lane >> 2;
    const int qq   = lane & 3;
    const int row0 = blockIdx.y * 128;
    const int col0 = blockIdx.x * 128;

    const int kq = tid & 3, rb = tid >> 2;
    const __half* Ag = A  + (size_t)(row0 + rb) * K + kq * 8;
    const __half* Bg = Bm + (size_t)(col0 + rb) * K + kq * 8;
    const uint32_t sA = s2u(As), sB = s2u(Bs);
    const uint32_t d0 = (uint32_t)(rb * 32 + ((kq ^ ((rb >> 1) & 3)) << 3)) * 2;

    const int rowA = lane & 15, hiA = lane >> 4;
    const int rowB = (lane & 7) + 8 * (lane >> 4), hiB = (lane >> 3) & 1;
    uint32_t aOff[4], bOff[4];
    int aSw[4], bSw[4];
#pragma unroll
    for (int i = 0; i < 4; ++i) {
        int r = wm * 64 + i * 16 + rowA;
        aOff[i] = (uint32_t)r * 64; aSw[i] = (r >> 1) & 3;
    }
#pragma unroll
    for (int p = 0; p < 4; ++p) {
        int r = wn * 64 + p * 16 + rowB;
        bOff[p] = (uint32_t)r * 64; bSw[p] = (r >> 1) & 3;
    }

    float acc[4][8][4];
#pragma unroll
    for (int i = 0; i < 4; ++i)
#pragma unroll
        for (int j = 0; j < 8; ++j)
#pragma unroll
            for (int v = 0; v < 4; ++v) acc[i][j][v] = 0.f;

    const int nk = K >> 5;

    auto issue = [&](int st) {
        const uint32_t ab = sA + (uint32_t)((st % NST) * GTILEH) * 2 + d0;
        const uint32_t bb = sB + (uint32_t)((st % NST) * GTILEH) * 2 + d0;
        const int kc = st << 5;
#pragma unroll
        for (int j = 0; j < 4; ++j) {
            cp16(ab + j * 2048, Ag + (size_t)(32 * j) * K + kc);
            cp16(bb + j * 2048, Bg + (size_t)(32 * j) * K + kc);
        }
    };

    issue(0); CP_COMMIT();
    issue(1); CP_COMMIT();
    issue(2); CP_COMMIT();

    for (int it = 0; it < nk; ++it) {
        CP_WAIT1();
        __syncthreads();
        if (it + 3 < nk) issue(it + 3);
        CP_COMMIT();

        const uint32_t aS = sA + (uint32_t)((it % NST) * GTILEH) * 2;
        const uint32_t bS = sB + (uint32_t)((it % NST) * GTILEH) * 2;
#pragma unroll
        for (int kk = 0; kk < 2; ++kk) {
            uint32_t af[4][4], bf[4][4];
#pragma unroll
            for (int i = 0; i < 4; ++i)
                ldsm4(af[i], aS + aOff[i] + (uint32_t)(((kk * 2 + hiA) ^ aSw[i]) << 4));
#pragma unroll
            for (int p = 0; p < 4; ++p)
                ldsm4(bf[p], bS + bOff[p] + (uint32_t)(((kk * 2 + hiB) ^ bSw[p]) << 4));
#pragma unroll
            for (int i = 0; i < 4; ++i)
#pragma unroll
                for (int j = 0; j < 8; ++j)
                    mma_f16(acc[i][j], af[i], &bf[j >> 1][(j & 1) * 2]);
        }
    }

    if (mode == 0) {
        const int egc = qq * 2;
#pragma unroll
        for (int i = 0; i < 4; ++i) {
#pragma unroll
            for (int j = 0; j < 8; ++j) {
                const size_t base = (size_t)(row0 + wm * 64 + i * 16 + gr) * N +
                                    col0 + wn * 64 + j * 8 + egc;
                *(float2*)(Cf + base) = make_float2(acc[i][j][0], acc[i][j][1]);
                *(float2*)(Cf + base + 8 * (size_t)N) = make_float2(acc[i][j][2], acc[i][j][3]);
            }
        }
        return;
    }

    // ---- fused qkv epilogue ----
    CP_WAIT0();
    __syncthreads();
    float* red = (float*)smh;
    const bool isV = (col0 >= DMODEL + NKV * HD);
    const bool isQ = (col0 < DMODEL);

    if (!isV) {
#pragma unroll
        for (int i = 0; i < 4; ++i) {
            float p0 = 0.f, p1 = 0.f;
#pragma unroll
            for (int j = 0; j < 8; ++j) {
                p0 += acc[i][j][0] * acc[i][j][0] + acc[i][j][1] * acc[i][j][1];
                p1 += acc[i][j][2] * acc[i][j][2] + acc[i][j][3] * acc[i][j][3];
            }
            p0 += __shfl_xor_sync(0xffffffffu, p0, 1);
            p0 += __shfl_xor_sync(0xffffffffu, p0, 2);
            p1 += __shfl_xor_sync(0xffffffffu, p1, 1);
            p1 += __shfl_xor_sync(0xffffffffu, p1, 2);
            if (qq == 0) {
                red[(wm * 64 + i * 16 + gr) * 2 + wn]     = p0;
                red[(wm * 64 + i * 16 + gr + 8) * 2 + wn] = p1;
            }
        }
        __syncthreads();
    }

    const float* nw = isQ ? qw : kw;
    const float qs = isQ ? (0.08838834764831845f * 1.44269504088896341f) : 1.0f;

#pragma unroll
    for (int i = 0; i < 4; ++i) {
        const int lra = wm * 64 + i * 16 + gr;
        const int lrb = lra + 8;
        const int ra = row0 + lra, rbg = row0 + lrb;
        float rsA = 1.f, rsB = 1.f;
        if (!isV) {
            rsA = rsqrtf((red[lra * 2] + red[lra * 2 + 1]) * (1.f / HD) + 1e-5f);
            rsB = rsqrtf((red[lrb * 2] + red[lrb * 2 + 1]) * (1.f / HD) + 1e-5f);
        }
        const int sa = ra & (SEQ - 1), sb = rbg & (SEQ - 1);
#pragma unroll
        for (int j = 0; j < 8; ++j) {
            const int cb = wn * 64 + j * 8 + 2 * qq;
            if (isV) {
                const int vc = (col0 - DMODEL - NKV * HD) + cb;
                *(__half2*)(g_vh + (size_t)ra  * (NKV * HD) + vc) =
                    __floats2half2_rn(acc[i][j][0], acc[i][j][1]);
                *(__half2*)(g_vh + (size_t)rbg * (NKV * HD) + vc) =
                    __floats2half2_rn(acc[i][j][2], acc[i][j][3]);
            } else {
                const float we = nw[cb], wo_ = nw[cb + 1];
                float2 fa = *(const float2*)(freqs + (size_t)sa * HD + cb);
                float xe = acc[i][j][0] * rsA * we;
                float xo = acc[i][j][1] * rsA * wo_;
                float oe = xe * fa.x - xo * fa.y;
                float oo = xo * fa.x + xe * fa.y;
                __half2 ha = __floats2half2_rn(oe * qs, oo * qs);
                float2 fb = *(const float2*)(freqs + (size_t)sb * HD + cb);
                xe = acc[i][j][2] * rsB * we;
                xo = acc[i][j][3] * rsB * wo_;
                oe = xe * fb.x - xo * fb.y;
                oo = xo * fb.x + xe * fb.y;
                __half2 hb = __floats2half2_rn(oe * qs, oo * qs);
                if (isQ) {
                    *(__half2*)(g_qh + (size_t)ra  * (NH * HD) + col0 + cb) = ha;
                    *(__half2*)(g_qh + (size_t)rbg * (NH * HD) + col0 + cb) = hb;
                } else {
                    const int kc = (col0 - DMODEL) + cb;
                    *(__half2*)(g_kh + (size_t)ra  * (NKV * HD) + kc) = ha;
                    *(__half2*)(g_kh + (size_t)rbg * (NKV * HD) + kc) = hb;
                }
            }
        }
    }
}

// ---------------------------------------------------------------------------
// Flash attention (R13 structure): 64-row Q tile, 128 threads, 2 CTAs/SM.
// Fixed-base softmax folded into accumulator init (-6); ex2.approx.f32;
// register-resident P; hoisted Q fragments; l via ones-column MMA.
// ---------------------------------------------------------------------------
#define SM_BIAS 6.0f
#define QS 136
#define KS 136
#define VS 152
#define KT (64 * KS)
#define VT (64 * VS)
#define ASMEM ((64 * QS + 2 * KT + 2 * VT) * 2)   // 91136 B

__global__ __launch_bounds__(128, 2)
void attn_hp()
{
    extern __shared__ __half smh[];
    __half* Qsm = smh;
    __half* Ksm = Qsm + 64 * QS;
    __half* Vsm = Ksm + 2 * KT;
    const uint32_t qB = s2u(Qsm), kB0 = s2u(Ksm), vB0 = s2u(Vsm);

    const int qt  = (int)gridDim.x - 1 - (int)blockIdx.x;
    const int h   = blockIdx.y;
    const int b   = blockIdx.z;
    const int kvh = h >> 2;
    const int q0  = qt * 64;
    const int tid = threadIdx.x;
    const int w   = tid >> 5;
    const int lane = tid & 31;
    const int gr  = lane >> 2;
    const int qq  = lane & 3;
    const int r0l = w * 16 + gr;
    const int r1l = r0l + 8;

    const int rowA = lane & 15;
    const int rowB = (lane & 7) + 8 * (lane >> 4);
    const int colA = 8 * (lane >> 4), colB = 8 * ((lane >> 3) & 1);
    const uint32_t qAddr = qB + (uint32_t)((w * 16 + rowA) * QS + colA) * 2;
    const uint32_t kOff  = (uint32_t)(rowB * KS + colB) * 2;
    const uint32_t vOff  = (uint32_t)((lane & 15) * VS + 8 * (lane >> 4)) * 2;

    const int sr = tid >> 4, sc = (tid & 15) * 8;
    auto stageK = [&](int kt, int buf) {
        const __half* src = g_kh + (size_t)(b * SEQ + kt * 64 + sr) * (NKV * HD) + kvh * HD + sc;
        uint32_t dst = kB0 + (uint32_t)(buf * KT) * 2 + (uint32_t)(sr * KS + sc) * 2;
#pragma unroll
        for (int it = 0; it < 8; ++it)
            cp16(dst + (uint32_t)(8 * it * KS) * 2, src + (size_t)(8 * it) * (NKV * HD));
    };
    auto stageV = [&](int kt, int buf) {
        const __half* src = g_vh + (size_t)(b * SEQ + kt * 64 + sr) * (NKV * HD) + kvh * HD + sc;
        uint32_t dst = vB0 + (uint32_t)(buf * VT) * 2 + (uint32_t)(sr * VS + sc) * 2;
#pragma unroll
        for (int it = 0; it < 8; ++it)
            cp16(dst + (uint32_t)(8 * it * VS) * 2, src + (size_t)(8 * it) * (NKV * HD));
    };

    // prologue: Q + K0 + V0; ones-column init in both V buffers
    {
        const __half* src = g_qh + (size_t)(b * SEQ + q0 + sr) * (NH * HD) + h * HD + sc;
        uint32_t dst = qB + (uint32_t)(sr * QS + sc) * 2;
#pragma unroll
        for (int it = 0; it < 8; ++it)
            cp16(dst + (uint32_t)(8 * it * QS) * 2, src + (size_t)(8 * it) * (NH * HD));
        stageK(0, 0); stageV(0, 0);
        CP_COMMIT();
        for (int idx = tid; idx < 2 * 64 * 16; idx += 128) {
            int bu = idx >> 10, r = (idx >> 4) & 63, c = idx & 15;
            Vsm[bu * VT + r * VS + 128 + c] = (c == 0) ? __float2half(1.f) : __float2half(0.f);
        }
        CP_WAIT0();
        __syncthreads();
    }

    // hoist Q fragments (loop-invariant)
    uint32_t qf[8][4];
#pragma unroll
    for (int kk = 0; kk < 8; ++kk)
        ldsm4(qf[kk], qAddr + (uint32_t)(kk * 16) * 2);

    float O[17][4];   // 16 hd tiles + 1 l tile
#pragma unroll
    for (int nt = 0; nt < 17; ++nt)
#pragma unroll
        for (int v = 0; v < 4; ++v) O[nt][v] = 0.f;

    for (int kt = 0; kt <= qt; ++kt) {
        if (kt < qt) {
            stageK(kt + 1, (kt + 1) & 1);
            stageV(kt + 1, (kt + 1) & 1);
            CP_COMMIT();
        }
        const uint32_t kAddr = kB0 + (uint32_t)((kt & 1) * KT) * 2 + kOff;
        const uint32_t vAddr = vB0 + (uint32_t)((kt & 1) * VT) * 2 + vOff;

        // S = Q K^T (accumulator pre-biased to -SM_BIAS)
        float s[8][4];
#pragma unroll
        for (int nt = 0; nt < 8; ++nt)
#pragma unroll
            for (int v = 0; v < 4; ++v) s[nt][v] = -SM_BIAS;
#pragma unroll
        for (int kk = 0; kk < 8; ++kk) {
            uint32_t bf[4][4];
#pragma unroll
            for (int p = 0; p < 4; ++p)
                ldsm4(bf[p], kAddr + (uint32_t)(p * 16 * KS + kk * 16) * 2);
#pragma unroll
            for (int nt = 0; nt < 8; ++nt)
                mma_f16(s[nt], qf[kk], &bf[nt >> 1][(nt & 1) * 2]);
        }

        // fixed-base softmax -> P fragments in registers
        if (kt == qt) {
#pragma unroll
            for (int nt = 0; nt < 8; ++nt) {
                int cb = nt * 8 + 2 * qq;
                if (cb     > r0l) s[nt][0] = -1e30f;
                if (cb + 1 > r0l) s[nt][1] = -1e30f;
                if (cb     > r1l) s[nt][2] = -1e30f;
                if (cb + 1 > r1l) s[nt][3] = -1e30f;
            }
        }
        uint32_t pa[8], pb[8];
#pragma unroll
        for (int nt = 0; nt < 8; ++nt) {
            pa[nt] = h2u(__floats2half2_rn(ex2f(s[nt][0]), ex2f(s[nt][1])));
            pb[nt] = h2u(__floats2half2_rn(ex2f(s[nt][2]), ex2f(s[nt][3])));
        }

        // O += P V  (+ l via ones column); P direct from registers
#pragma unroll
        for (int kk = 0; kk < 4; ++kk) {
            uint32_t af[4] = {pa[2 * kk], pb[2 * kk], pa[2 * kk + 1], pb[2 * kk + 1]};
            uint32_t bf[8][4], b8[4];
#pragma unroll
            for (int p = 0; p < 8; ++p)
                ldsm4t(bf[p], vAddr + (uint32_t)(kk * 16 * VS + p * 16) * 2);
            ldsm4t(b8, vAddr + (uint32_t)(kk * 16 * VS + 128) * 2);
#pragma unroll
            for (int nt = 0; nt < 16; ++nt)
                mma_f16(O[nt], af, &bf[nt >> 1][(nt & 1) * 2]);
            mma_f16(O[16], af, &b8[0]);
        }

        if (kt < qt) {
            CP_WAIT0();
            __syncthreads();
        }
    }

    float l0 = __shfl_sync(0xffffffffu, O[16][0], lane & ~3);
    float l1 = __shfl_sync(0xffffffffu, O[16][2], lane & ~3);
    float inv0 = 1.f / l0, inv1 = 1.f / l1;
    __half* y0 = g_yh + (size_t)(b * SEQ + q0 + r0l) * (NH * HD) + h * HD;
    __half* y1 = g_yh + (size_t)(b * SEQ + q0 + r1l) * (NH * HD) + h * HD;
#pragma unroll
    for (int nt = 0; nt < 16; ++nt) {
        *(__half2*)(y0 + nt * 8 + 2 * qq) = __floats2half2_rn(O[nt][0] * inv0, O[nt][1] * inv0);
        *(__half2*)(y1 + nt * 8 + 2 * qq) = __floats2half2_rn(O[nt][2] * inv1, O[nt][3] * inv1);
    }
}

// ---------------------------------------------------------------------------
extern "C" void kernel_launch(void* const* d_in, const int* in_sizes, int n_in,
                              void* d_out, int out_size)
{
    const float* x    = (const float*)d_in[0];
    const float* fr   = (const float*)d_in[1];
    const float* wqkv = (const float*)d_in[3];
    const float* wo   = (const float*)d_in[4];
    const float* qw   = (const float*)d_in[5];
    const float* kw   = (const float*)d_in[6];
    float* out = (float*)d_out;

    __half *yh_p, *xh_p, *wqkvh_p, *woh_p;
    cudaGetSymbolAddress((void**)&yh_p,    g_yh);
    cudaGetSymbolAddress((void**)&xh_p,    g_xh);
    cudaGetSymbolAddress((void**)&wqkvh_p, g_wqkvh);
    cudaGetSymbolAddress((void**)&woh_p,   g_woh);

    // 0) Convert inputs/weights to fp16 (single launch)
    const size_t ntot = N_X + N_W1 + N_W2;
    to_half_all<<<(unsigned)(ntot / 1024), 256>>>(x, wqkv, wo);

    cudaFuncSetAttribute(gemm_hp, cudaFuncAttributeMaxDynamicSharedMemorySize, GSMEM);
    cudaFuncSetAttribute(attn_hp, cudaFuncAttributeMaxDynamicSharedMemorySize, ASMEM);

    // 1) QKV projection + fused RMSNorm/RoPE/scale epilogue
    gemm_hp<<<dim3(EQKV / 128, TOK / 128), 128, GSMEM>>>(
        xh_p, wqkvh_p, nullptr, TOK, EQKV, DMODEL, 1, fr, qw, kw);

    // 2) Causal GQA flash attention (64-row q tiles, 2 CTAs/SM)
    attn_hp<<<dim3(SEQ / 64, NH, BATCH), 128, ASMEM>>>();

    // 3) Output projection (fp32 out)
    gemm_hp<<<dim3(DMODEL / 128, TOK / 128), 128, GSMEM>>>(
        yh_p, woh_p, out, TOK, DMODEL, DMODEL, 0, nullptr, nullptr, nullptr);
}